// round 14
// baseline (speedup 1.0000x reference)
#include <cuda_runtime.h>
#include <cuda_fp16.h>
#include <math.h>
#include <float.h>
#include <stdint.h>

// ---------------- problem constants (fixed by dataset) ----------------
#define N_Q   65      // n = 1+W
#define M_KV  129     // m = 1+R
#define NH    8       // heads
#define HDIM  64      // head dim
#define CDIM  512     // model dim (= H*HD)
#define BQMAX 512     // B_ = 512

// ---------------- scratch (device globals; no allocation) -------------
__device__ __half h_x  [(size_t)BQMAX * N_Q  * CDIM];
__device__ __half h_x_ [(size_t)BQMAX * M_KV * CDIM];
__device__ __half h_wq [(size_t)CDIM * CDIM];
__device__ __half h_wkv[(size_t)2 * CDIM * CDIM];
__device__ __half h_wp [(size_t)CDIM * CDIM];
__device__ __half h_q  [(size_t)BQMAX * N_Q  * CDIM];
__device__ __half h_kv [(size_t)BQMAX * M_KV * 2 * CDIM];
__device__ __half h_att[(size_t)BQMAX * N_Q  * CDIM];
// bias+mask tables: 9 window classes x 8 heads x 65 x 132 fp32
__device__ float g_bias[(size_t)9 * NH * N_Q * 132];

// ---------------- helpers ----------------------------------------------
__device__ __forceinline__ void mma_f16(float c[4], const uint32_t a[4],
                                        const uint32_t b[2]) {
    asm volatile(
        "mma.sync.aligned.m16n8k16.row.col.f32.f16.f16.f32 "
        "{%0,%1,%2,%3}, {%4,%5,%6,%7}, {%8,%9}, {%0,%1,%2,%3};"
        : "+f"(c[0]), "+f"(c[1]), "+f"(c[2]), "+f"(c[3])
        : "r"(a[0]), "r"(a[1]), "r"(a[2]), "r"(a[3]),
          "r"(b[0]), "r"(b[1]));
}
__device__ __forceinline__ void cp16(void* smem, const void* g) {
    uint32_t a = (uint32_t)__cvta_generic_to_shared(smem);
    asm volatile("cp.async.cg.shared.global [%0], [%1], 16;\n"
                 :: "r"(a), "l"(g));
}
__device__ __forceinline__ uint32_t h2u(__half2 h) {
    return *reinterpret_cast<uint32_t*>(&h);
}
__device__ __forceinline__ uint32_t s2u(const void* p) {
    return (uint32_t)__cvta_generic_to_shared(p);
}
__device__ __forceinline__ void ldsm_x4(uint32_t r[4], uint32_t addr) {
    asm volatile("ldmatrix.sync.aligned.m8n8.x4.shared.b16 {%0,%1,%2,%3}, [%4];"
                 : "=r"(r[0]), "=r"(r[1]), "=r"(r[2]), "=r"(r[3]) : "r"(addr));
}
__device__ __forceinline__ void ldsm_x2(uint32_t r[2], uint32_t addr) {
    asm volatile("ldmatrix.sync.aligned.m8n8.x2.shared.b16 {%0,%1}, [%2];"
                 : "=r"(r[0]), "=r"(r[1]) : "r"(addr));
}
__device__ __forceinline__ void ldsm_x2_trans(uint32_t r[2], uint32_t addr) {
    asm volatile("ldmatrix.sync.aligned.m8n8.x2.trans.shared.b16 {%0,%1}, [%2];"
                 : "=r"(r[0]), "=r"(r[1]) : "r"(addr));
}

// =======================================================================
// fp32 -> fp16 conversion pre-pass, all 5 tensors in ONE launch.
// =======================================================================
__global__ void cvt_fp16_multi(
    const float* __restrict__ s0, __half* __restrict__ d0, int n0,
    const float* __restrict__ s1, __half* __restrict__ d1, int n1,
    const float* __restrict__ s2, __half* __restrict__ d2, int n2,
    const float* __restrict__ s3, __half* __restrict__ d3, int n3,
    const float* __restrict__ s4, __half* __restrict__ d4, int n4)
{
    int i = blockIdx.x * blockDim.x + threadIdx.x;
    const float* s; __half* d; int l = i;
    if (l < n0)                  { s = s0; d = d0; }
    else if ((l -= n0) < n1)     { s = s1; d = d1; }
    else if ((l -= n1) < n2)     { s = s2; d = d2; }
    else if ((l -= n2) < n3)     { s = s3; d = d3; }
    else if ((l -= n3) < n4)     { s = s4; d = d4; }
    else return;
    const float4 v0 = ((const float4*)s)[l * 2];
    const float4 v1 = ((const float4*)s)[l * 2 + 1];
    uint4 o;
    o.x = h2u(__floats2half2_rn(v0.x, v0.y));
    o.y = h2u(__floats2half2_rn(v0.z, v0.w));
    o.z = h2u(__floats2half2_rn(v1.x, v1.y));
    o.w = h2u(__floats2half2_rn(v1.z, v1.w));
    ((uint4*)d)[l] = o;
}

// =======================================================================
// bias+mask table build: 72 blocks = (cls 0..8) x (h 0..7).
// =======================================================================
__global__ void build_bias_kernel(
    const float* __restrict__ rel, const float* __restrict__ self_,
    const float* __restrict__ up,  const float* __restrict__ down,
    const int* __restrict__ ml,    const int* __restrict__ mr)
{
    const int cls = blockIdx.x >> 3;
    const int h   = blockIdx.x & 7;
    float* dst = g_bias + ((size_t)(cls * NH + h)) * N_Q * 132;
    for (int idx = threadIdx.x; idx < N_Q * M_KV; idx += 256) {
        int i = idx / M_KV, j = idx % M_KV;
        float bias;
        if (i == 0)      bias = (j == 0) ? self_[h] : up[h * 128 + (j - 1)];
        else if (j == 0) bias = down[h * 64 + (i - 1)];
        else             bias = rel[(i - j + 127) * NH + h];
        if (cls >= 1 && cls <= 4) {
            if (ml[((cls - 1) * N_Q + i) * M_KV + j] == 1) bias = -FLT_MAX;
        } else if (cls >= 5) {
            if (mr[((cls - 5) * N_Q + i) * M_KV + j] == 1) bias = -FLT_MAX;
        }
        dst[i * 132 + j] = bias;
    }
    for (int idx = threadIdx.x; idx < N_Q * 3; idx += 256) {
        int i = idx / 3, c = M_KV + idx % 3;
        dst[i * 132 + c] = 0.f;
    }
}

// =======================================================================
// FP16 tensor-core GEMM, WIDE CTA: BM=128, BN=256, BK=64, 512 threads
// (16 warps = 2(M) x 8(N)), warp tile 64x32 (identical per-warp code to
// the proven R13 kernel -> bit-identical output).
//   C[M,N] = (A[M,K] @ W[N,K]^T + bias[N]) * outScale
// Requires M%128==0, N%256==0, K%64==0.
// =======================================================================
#define GBM 128
#define GBN 256
#define GBK 64
#define A_TILE_B (128 * 128)                  // 16384 B
#define B_TILE_B (256 * 128)                  // 32768 B
#define STAGE_B  (A_TILE_B + B_TILE_B)        // 49152 B
#define GEMM_SMEM_BYTES (2 * STAGE_B)         // 98304 B

__global__ __launch_bounds__(512, 1) void gemm_f16_kernel(
    const __half* __restrict__ A, const __half* __restrict__ W,
    const float* __restrict__ bias, void* __restrict__ Cv,
    int K, int N, int outHalf, float outScale)
{
    extern __shared__ char smem[];

    const int tid    = threadIdx.x;
    const int warp   = tid >> 5;
    const int lane   = tid & 31;
    const int quad   = lane >> 2;
    const int tq     = lane & 3;
    const int lo7    = lane & 7;
    const int l3     = (lane >> 3) & 1;
    const int hi     = lane >> 4;
    const int warp_m = warp >> 3;          // 0..1 (64 rows)
    const int warp_n = warp & 7;           // 0..7 (32 cols)
    const int rowBase = blockIdx.y * GBM;
    const int colBase = blockIdx.x * GBN;

    const __half* Ap = A + (size_t)rowBase * K;
    const __half* Wp = W + (size_t)colBase * K;

    float acc[4][4][4];
#pragma unroll
    for (int mt = 0; mt < 4; mt++)
#pragma unroll
        for (int nt = 0; nt < 4; nt++)
#pragma unroll
            for (int r = 0; r < 4; r++) acc[mt][nt][r] = 0.f;

    const uint32_t sbase = s2u(smem);
    const uint32_t aRow = (uint32_t)((warp_m * 64 + lo7 + 8 * l3) * 128);
    const uint32_t bRow = (uint32_t)((warp_n * 32 + lo7) * 128);

    const int NITER = K >> 6;

    // producer: A 1024 chunks (2/thread), B 2048 chunks (4/thread)
    auto issue = [&](int it) {
        char* aS = smem + (it & 1) * STAGE_B;
        char* bS = aS + A_TILE_B;
        const int k0 = it * GBK;
#pragma unroll
        for (int i = 0; i < 2; i++) {
            int f   = tid + i * 512;
            int r   = f >> 3;
            int seg = f & 7;
            int dst = r * 128 + ((seg ^ (r & 7)) * 16);
            cp16(aS + dst, Ap + (size_t)r * K + k0 + seg * 8);
        }
#pragma unroll
        for (int i = 0; i < 4; i++) {
            int f   = tid + i * 512;
            int r   = f >> 3;
            int seg = f & 7;
            int dst = r * 128 + ((seg ^ (r & 7)) * 16);
            cp16(bS + dst, Wp + (size_t)r * K + k0 + seg * 8);
        }
    };

    issue(0);
    asm volatile("cp.async.commit_group;\n");

    for (int it = 0; it < NITER; it++) {
        if (it + 1 < NITER) {
            issue(it + 1);
            asm volatile("cp.async.commit_group;\n");
            asm volatile("cp.async.wait_group 1;\n");
        } else {
            asm volatile("cp.async.wait_group 0;\n");
        }
        __syncthreads();

        const uint32_t aBase = sbase + (it & 1) * STAGE_B;
        const uint32_t bBase = aBase + A_TILE_B;

#pragma unroll
        for (int ks = 0; ks < 4; ks++) {
            const uint32_t aSeg = (uint32_t)(((2 * ks + hi) ^ lo7) * 16);
            const uint32_t bSeg = (uint32_t)(((2 * ks + l3) ^ lo7) * 16);
            uint32_t af[4][4];
            uint32_t bf[4][2];
#pragma unroll
            for (int mt = 0; mt < 4; mt++)
                ldsm_x4(af[mt], aBase + aRow + (uint32_t)(mt * 16 * 128) + aSeg);
#pragma unroll
            for (int nt = 0; nt < 4; nt++)
                ldsm_x2(bf[nt], bBase + bRow + (uint32_t)(nt * 8 * 128) + bSeg);
#pragma unroll
            for (int mt = 0; mt < 4; mt++)
#pragma unroll
                for (int nt = 0; nt < 4; nt++)
                    mma_f16(acc[mt][nt], af[mt], bf[nt]);
        }
        __syncthreads();
    }

#pragma unroll
    for (int mt = 0; mt < 4; mt++) {
        int r0 = rowBase + warp_m * 64 + mt * 16 + quad;
#pragma unroll
        for (int nt = 0; nt < 4; nt++) {
            int c = colBase + warp_n * 32 + nt * 8 + 2 * tq;
            float2 bv = *(const float2*)&bias[c];
            float ox0 = (acc[mt][nt][0] + bv.x) * outScale;
            float oy0 = (acc[mt][nt][1] + bv.y) * outScale;
            float ox1 = (acc[mt][nt][2] + bv.x) * outScale;
            float oy1 = (acc[mt][nt][3] + bv.y) * outScale;
            if (outHalf) {
                __half* Ch = (__half*)Cv;
                *(uint32_t*)&Ch[(size_t)r0 * N + c] =
                    h2u(__floats2half2_rn(ox0, oy0));
                *(uint32_t*)&Ch[(size_t)(r0 + 8) * N + c] =
                    h2u(__floats2half2_rn(ox1, oy1));
            } else {
                float* Cf = (float*)Cv;
                *(float2*)&Cf[(size_t)r0 * N + c]       = make_float2(ox0, oy0);
                *(float2*)&Cf[(size_t)(r0 + 8) * N + c] = make_float2(ox1, oy1);
            }
        }
    }
}

// =======================================================================
// FP16 fused window attention (unchanged from R13)
// =======================================================================
#define QKH 72
#define PVH 152
#define SSW 132
#define R1_W   4940
#define R2_W   5184
#define OFF_S  (R1_W + R2_W)
#define ATTN_W (OFF_S + N_Q * SSW)
#define ATTN_SMEM_BYTES (ATTN_W * 4)

__global__ __launch_bounds__(256, 3) void attn_kernel(
    const int* __restrict__ nW_ptr,
    __half* __restrict__ out)
{
    extern __shared__ float sm[];
    __half* qh  = (__half*)sm;
    __half* ph  = (__half*)sm;
    __half* kh  = (__half*)(sm + R1_W);
    __half* vh  = (__half*)(sm + R1_W);
    float*  S   = sm + OFF_S;

    const int bid  = blockIdx.x;
    const int b    = bid >> 3;
    const int h    = bid & 7;
    const int tid  = threadIdx.x;
    const int warp = tid >> 5;
    const int lane = tid & 31;
    const int quad = lane >> 2;
    const int tq   = lane & 3;
    const int lo7  = lane & 7;
    const int l3   = (lane >> 3) & 1;
    const int hi   = lane >> 4;
    const int wm   = warp >> 1;
    const int wn   = warp & 1;
    const int nW   = *nW_ptr;

    const int mc = (nW < 4) ? nW : 4;
    const int w  = b % nW;
    int cls = 0;
    if (w < mc)            cls = 1 + w;
    else if (w >= nW - mc) cls = 5 + (w - nW + 4);
    const float* T = g_bias + ((size_t)(cls * NH + h)) * N_Q * 132;

    for (int idx = tid; idx < (N_Q * SSW) / 4; idx += 256)
        *(float4*)&S[idx * 4] = *(const float4*)&T[idx * 4];

    for (int idx = tid; idx < N_Q * 8; idx += 256) {
        int i = idx >> 3, c = idx & 7;
        uint4 v = *(const uint4*)&h_q[((size_t)(b * N_Q + i)) * CDIM + h * HDIM + c * 8];
        *(uint4*)&qh[i * QKH + c * 8] = v;
    }
    for (int idx = tid; idx < 144 * 8; idx += 256) {
        int j = idx >> 3, c = idx & 7;
        uint4 v = {0u, 0u, 0u, 0u};
        if (j < M_KV)
            v = *(const uint4*)&h_kv[((size_t)(b * M_KV + j)) * (2 * CDIM)
                                     + h * HDIM + c * 8];
        *(uint4*)&kh[j * QKH + c * 8] = v;
    }
    __syncthreads();

    const int nbase = wn * 72;
    float acc[9][4];
#pragma unroll
    for (int nt = 0; nt < 9; nt++)
#pragma unroll
        for (int r = 0; r < 4; r++) acc[nt][r] = 0.f;

    {
        const uint32_t qB = s2u(qh) + (uint32_t)((wm * 16 + lo7 + 8 * l3) * 144);
        const uint32_t kB = s2u(kh) + (uint32_t)((nbase + lo7) * 144);
#pragma unroll
        for (int ks = 0; ks < 4; ks++) {
            uint32_t a[4];
            ldsm_x4(a, qB + (uint32_t)(ks * 32 + 16 * hi));
#pragma unroll
            for (int nt = 0; nt < 9; nt++) {
                uint32_t bfr[2];
                ldsm_x2(bfr, kB + (uint32_t)(nt * 8 * 144 + ks * 32 + 16 * l3));
                mma_f16(acc[nt], a, bfr);
            }
        }
    }

    float s64 = 0.f;
    if (tid < M_KV) {
#pragma unroll 8
        for (int d = 0; d < HDIM; d++)
            s64 += __half2float(qh[64 * QKH + d]) * __half2float(kh[tid * QKH + d]);
    }
    __syncthreads();

#pragma unroll
    for (int nt = 0; nt < 9; nt++) {
        int j0 = nbase + nt * 8 + 2 * tq;
        int i0 = wm * 16 + quad;
#pragma unroll
        for (int e = 0; e < 4; e++) {
            int i = i0 + (e >> 1) * 8;
            int j = j0 + (e & 1);
            if (j >= M_KV) continue;
            S[i * SSW + j] = acc[nt][e] + S[i * SSW + j];
        }
    }
    if (tid < M_KV)
        S[64 * SSW + tid] = s64 + S[64 * SSW + tid];

    for (int idx = tid; idx < N_Q * 15; idx += 256) {
        int i = idx / 15, c = M_KV + idx % 15;
        ph[i * PVH + c] = __float2half(0.f);
    }
    for (int idx = tid; idx < 144 * 8; idx += 256) {
        int j = idx >> 3, c = idx & 7;
        uint4 v = {0u, 0u, 0u, 0u};
        if (j < M_KV)
            v = *(const uint4*)&h_kv[((size_t)(b * M_KV + j)) * (2 * CDIM)
                                     + CDIM + h * HDIM + c * 8];
        *(uint4*)&vh[j * QKH + c * 8] = v;
    }
    __syncthreads();

    for (int r = warp; r < N_Q; r += 8) {
        float mx = -FLT_MAX;
        for (int c = lane; c < M_KV; c += 32) mx = fmaxf(mx, S[r * SSW + c]);
#pragma unroll
        for (int o = 16; o; o >>= 1) mx = fmaxf(mx, __shfl_xor_sync(0xffffffffu, mx, o));
        float sum = 0.f;
        float ev[5];
#pragma unroll
        for (int t = 0; t < 5; t++) {
            int c = lane + t * 32;
            float e = (c < M_KV) ? __expf(S[r * SSW + c] - mx) : 0.f;
            ev[t] = e;
            sum += e;
        }
#pragma unroll
        for (int o = 16; o; o >>= 1) sum += __shfl_xor_sync(0xffffffffu, sum, o);
        float inv = 1.0f / sum;
#pragma unroll
        for (int t = 0; t < 5; t++) {
            int c = lane + t * 32;
            if (c < M_KV) ph[r * PVH + c] = __float2half_rn(ev[t] * inv);
        }
    }
    __syncthreads();

    float acc2[4][4];
#pragma unroll
    for (int nt = 0; nt < 4; nt++)
#pragma unroll
        for (int r = 0; r < 4; r++) acc2[nt][r] = 0.f;

    {
        const uint32_t pB = s2u(ph) + (uint32_t)((wm * 16 + lo7 + 8 * l3) * 304);
        const uint32_t vB = s2u(vh) + (uint32_t)((lane & 15) * 144 + wn * 64);
#pragma unroll
        for (int ks = 0; ks < 9; ks++) {
            uint32_t a[4];
            ldsm_x4(a, pB + (uint32_t)(ks * 32 + 16 * hi));
#pragma unroll
            for (int nt = 0; nt < 4; nt++) {
                uint32_t bfr[2];
                ldsm_x2_trans(bfr, vB + (uint32_t)(ks * 16 * 144 + nt * 16));
                mma_f16(acc2[nt], a, bfr);
            }
        }
    }

    float o64 = 0.f;
    if (tid < HDIM) {
        for (int j = 0; j < M_KV; j++)
            o64 += __half2float(ph[64 * PVH + j]) * __half2float(vh[j * QKH + tid]);
    }

#pragma unroll
    for (int nt = 0; nt < 4; nt++) {
        int i0 = wm * 16 + quad;
        int d0 = wn * 32 + nt * 8 + 2 * tq;
        *(uint32_t*)&out[((size_t)(b * N_Q + i0)) * CDIM + h * HDIM + d0] =
            h2u(__floats2half2_rn(acc2[nt][0], acc2[nt][1]));
        *(uint32_t*)&out[((size_t)(b * N_Q + i0 + 8)) * CDIM + h * HDIM + d0] =
            h2u(__floats2half2_rn(acc2[nt][2], acc2[nt][3]));
    }
    if (tid < HDIM)
        out[((size_t)(b * N_Q + 64)) * CDIM + h * HDIM + tid] = __float2half_rn(o64);
}

// =======================================================================
// kernel_launch
// =======================================================================
extern "C" void kernel_launch(void* const* d_in, const int* in_sizes, int n_in,
                              void* d_out, int out_size)
{
    const float* x    = (const float*)d_in[0];
    const float* x_   = (const float*)d_in[1];
    const int*   mask_left  = (const int*)d_in[2];
    const int*   mask_right = (const int*)d_in[3];
    const int*   nW   = (const int*)d_in[4];
    const float* rel_table = (const float*)d_in[5];
    const float* cls_self  = (const float*)d_in[6];
    const float* cls_up    = (const float*)d_in[7];
    const float* cls_down  = (const float*)d_in[8];
    const float* Wq   = (const float*)d_in[9];
    const float* bq   = (const float*)d_in[10];
    const float* Wkv  = (const float*)d_in[11];
    const float* bkv  = (const float*)d_in[12];
    const float* Wp   = (const float*)d_in[13];
    const float* bp   = (const float*)d_in[14];
    float* out = (float*)d_out;

    const int Bq = in_sizes[0] / (N_Q * CDIM);   // 512

    __half *hx, *hx_, *hwq, *hwkv, *hwp, *hq, *hkv, *hatt;
    cudaGetSymbolAddress((void**)&hx,   h_x);
    cudaGetSymbolAddress((void**)&hx_,  h_x_);
    cudaGetSymbolAddress((void**)&hwq,  h_wq);
    cudaGetSymbolAddress((void**)&hwkv, h_wkv);
    cudaGetSymbolAddress((void**)&hwp,  h_wp);
    cudaGetSymbolAddress((void**)&hq,   h_q);
    cudaGetSymbolAddress((void**)&hkv,  h_kv);
    cudaGetSymbolAddress((void**)&hatt, h_att);

    cudaFuncSetAttribute(gemm_f16_kernel,
                         cudaFuncAttributeMaxDynamicSharedMemorySize,
                         GEMM_SMEM_BYTES);
    cudaFuncSetAttribute(attn_kernel,
                         cudaFuncAttributeMaxDynamicSharedMemorySize,
                         ATTN_SMEM_BYTES);

    // 0a) bias+mask tables
    build_bias_kernel<<<9 * NH, 256>>>(rel_table, cls_self, cls_up, cls_down,
                                       mask_left, mask_right);
    // 0b) fp32 -> fp16 pre-pass
    {
        int n0 = Bq * N_Q * CDIM / 8;
        int n1 = Bq * M_KV * CDIM / 8;
        int n2 = CDIM * CDIM / 8;
        int n3 = 2 * CDIM * CDIM / 8;
        int n4 = CDIM * CDIM / 8;
        int total = n0 + n1 + n2 + n3 + n4;
        cvt_fp16_multi<<<(total + 255) / 256, 256>>>(
            x, hx, n0, x_, hx_, n1, Wq, hwq, n2, Wkv, hwkv, n3, Wp, hwp, n4);
    }

    // 1) q = (x @ Wq^T + bq) * 0.125 : M = 33280, N = 512 -> fp16
    {
        dim3 grid(CDIM / GBN, (Bq * N_Q) / GBM);          // (2, 260)
        gemm_f16_kernel<<<grid, 512, GEMM_SMEM_BYTES>>>(
            hx, hwq, bq, hq, CDIM, CDIM, 1, 0.125f);
    }
    // 2) kv = x_ @ Wkv^T + bkv : M = 66048, N = 1024 -> fp16
    {
        dim3 grid((2 * CDIM) / GBN, (Bq * M_KV) / GBM);   // (4, 516)
        gemm_f16_kernel<<<grid, 512, GEMM_SMEM_BYTES>>>(
            hx_, hwkv, bkv, hkv, CDIM, 2 * CDIM, 1, 1.0f);
    }
    // 3) fused fp16 attention -> h_att
    {
        attn_kernel<<<Bq * NH, 256, ATTN_SMEM_BYTES>>>(nW, hatt);
    }
    // 4) out = att @ Wp^T + bp : M = 33280, N = 512 -> fp32
    {
        dim3 grid(CDIM / GBN, (Bq * N_Q) / GBM);          // (2, 260)
        gemm_f16_kernel<<<grid, 512, GEMM_SMEM_BYTES>>>(
            hatt, hwp, bp, out, CDIM, CDIM, 0, 1.0f);
    }
}

// round 15
// speedup vs baseline: 1.0965x; 1.0965x over previous
#include <cuda_runtime.h>
#include <cuda_fp16.h>
#include <math.h>
#include <float.h>
#include <stdint.h>

// ---------------- problem constants (fixed by dataset) ----------------
#define N_Q   65      // n = 1+W
#define M_KV  129     // m = 1+R
#define NH    8       // heads
#define HDIM  64      // head dim
#define CDIM  512     // model dim (= H*HD)
#define BQMAX 512     // B_ = 512

// ---------------- scratch (device globals; no allocation) -------------
__device__ __half h_x  [(size_t)BQMAX * N_Q  * CDIM];
__device__ __half h_x_ [(size_t)BQMAX * M_KV * CDIM];
__device__ __half h_wq [(size_t)CDIM * CDIM];
__device__ __half h_wkv[(size_t)2 * CDIM * CDIM];
__device__ __half h_wp [(size_t)CDIM * CDIM];
__device__ __half h_q  [(size_t)BQMAX * N_Q  * CDIM];
__device__ __half h_kv [(size_t)BQMAX * M_KV * 2 * CDIM];
__device__ __half h_att[(size_t)BQMAX * N_Q  * CDIM];
// bias+mask tables: 9 window classes x 8 heads x 65 x 132 fp32
__device__ float g_bias[(size_t)9 * NH * N_Q * 132];

// ---------------- helpers ----------------------------------------------
__device__ __forceinline__ void mma_f16(float c[4], const uint32_t a[4],
                                        const uint32_t b[2]) {
    asm volatile(
        "mma.sync.aligned.m16n8k16.row.col.f32.f16.f16.f32 "
        "{%0,%1,%2,%3}, {%4,%5,%6,%7}, {%8,%9}, {%0,%1,%2,%3};"
        : "+f"(c[0]), "+f"(c[1]), "+f"(c[2]), "+f"(c[3])
        : "r"(a[0]), "r"(a[1]), "r"(a[2]), "r"(a[3]),
          "r"(b[0]), "r"(b[1]));
}
__device__ __forceinline__ void cp16(void* smem, const void* g) {
    uint32_t a = (uint32_t)__cvta_generic_to_shared(smem);
    asm volatile("cp.async.cg.shared.global [%0], [%1], 16;\n"
                 :: "r"(a), "l"(g));
}
__device__ __forceinline__ uint32_t h2u(__half2 h) {
    return *reinterpret_cast<uint32_t*>(&h);
}
__device__ __forceinline__ uint32_t s2u(const void* p) {
    return (uint32_t)__cvta_generic_to_shared(p);
}
__device__ __forceinline__ void ldsm_x4(uint32_t r[4], uint32_t addr) {
    asm volatile("ldmatrix.sync.aligned.m8n8.x4.shared.b16 {%0,%1,%2,%3}, [%4];"
                 : "=r"(r[0]), "=r"(r[1]), "=r"(r[2]), "=r"(r[3]) : "r"(addr));
}
__device__ __forceinline__ void ldsm_x2(uint32_t r[2], uint32_t addr) {
    asm volatile("ldmatrix.sync.aligned.m8n8.x2.shared.b16 {%0,%1}, [%2];"
                 : "=r"(r[0]), "=r"(r[1]) : "r"(addr));
}
__device__ __forceinline__ void ldsm_x2_trans(uint32_t r[2], uint32_t addr) {
    asm volatile("ldmatrix.sync.aligned.m8n8.x2.trans.shared.b16 {%0,%1}, [%2];"
                 : "=r"(r[0]), "=r"(r[1]) : "r"(addr));
}

// =======================================================================
// fp32 -> fp16 conversion pre-pass, all 5 tensors in ONE launch.
// =======================================================================
__global__ void cvt_fp16_multi(
    const float* __restrict__ s0, __half* __restrict__ d0, int n0,
    const float* __restrict__ s1, __half* __restrict__ d1, int n1,
    const float* __restrict__ s2, __half* __restrict__ d2, int n2,
    const float* __restrict__ s3, __half* __restrict__ d3, int n3,
    const float* __restrict__ s4, __half* __restrict__ d4, int n4)
{
    int i = blockIdx.x * blockDim.x + threadIdx.x;
    const float* s; __half* d; int l = i;
    if (l < n0)                  { s = s0; d = d0; }
    else if ((l -= n0) < n1)     { s = s1; d = d1; }
    else if ((l -= n1) < n2)     { s = s2; d = d2; }
    else if ((l -= n2) < n3)     { s = s3; d = d3; }
    else if ((l -= n3) < n4)     { s = s4; d = d4; }
    else return;
    const float4 v0 = ((const float4*)s)[l * 2];
    const float4 v1 = ((const float4*)s)[l * 2 + 1];
    uint4 o;
    o.x = h2u(__floats2half2_rn(v0.x, v0.y));
    o.y = h2u(__floats2half2_rn(v0.z, v0.w));
    o.z = h2u(__floats2half2_rn(v1.x, v1.y));
    o.w = h2u(__floats2half2_rn(v1.z, v1.w));
    ((uint4*)d)[l] = o;
}

// =======================================================================
// bias+mask table build: 72 blocks = (cls 0..8) x (h 0..7).
// =======================================================================
__global__ void build_bias_kernel(
    const float* __restrict__ rel, const float* __restrict__ self_,
    const float* __restrict__ up,  const float* __restrict__ down,
    const int* __restrict__ ml,    const int* __restrict__ mr)
{
    const int cls = blockIdx.x >> 3;
    const int h   = blockIdx.x & 7;
    float* dst = g_bias + ((size_t)(cls * NH + h)) * N_Q * 132;
    for (int idx = threadIdx.x; idx < N_Q * M_KV; idx += 256) {
        int i = idx / M_KV, j = idx % M_KV;
        float bias;
        if (i == 0)      bias = (j == 0) ? self_[h] : up[h * 128 + (j - 1)];
        else if (j == 0) bias = down[h * 64 + (i - 1)];
        else             bias = rel[(i - j + 127) * NH + h];
        if (cls >= 1 && cls <= 4) {
            if (ml[((cls - 1) * N_Q + i) * M_KV + j] == 1) bias = -FLT_MAX;
        } else if (cls >= 5) {
            if (mr[((cls - 5) * N_Q + i) * M_KV + j] == 1) bias = -FLT_MAX;
        }
        dst[i * 132 + j] = bias;
    }
    for (int idx = threadIdx.x; idx < N_Q * 3; idx += 256) {
        int i = idx / 3, c = M_KV + idx % 3;
        dst[i * 132 + c] = 0.f;
    }
}

// =======================================================================
// FP16 tensor-core GEMM — R13 shape (BM=128, BN=128, 256 thr, 2 CTA/SM)
// with 3-STAGE cp.async pipeline and ONE barrier per k-iter.
//   C[M,N] = (A[M,K] @ W[N,K]^T + bias[N]) * outScale
// Requires M%128==0, N%128==0, K%64==0.
// Stage safety (3 stages, sync before producer): issue(it+2) writes stage
// (it+2)%3 == (it-1)%3, whose readers (mma of it-1) all completed before
// any thread passed this iteration's __syncthreads. Data readiness:
// wait_group(1) leaves only group it+1 pending -> group it done for this
// thread; the following sync makes ALL threads' stage-it copies visible.
// =======================================================================
#define GBM 128
#define GBN 128
#define GBK 64
#define TILE_B   (128 * 128)                  // 16384 B per operand tile
#define STAGE_B  (2 * TILE_B)                 // A + B per stage
#define GEMM_SMEM_BYTES (3 * STAGE_B)         // 98304 B (3 stages)

__global__ __launch_bounds__(256, 2) void gemm_f16_kernel(
    const __half* __restrict__ A, const __half* __restrict__ W,
    const float* __restrict__ bias, void* __restrict__ Cv,
    int K, int N, int outHalf, float outScale)
{
    extern __shared__ char smem[];

    const int tid    = threadIdx.x;
    const int warp   = tid >> 5;
    const int lane   = tid & 31;
    const int quad   = lane >> 2;
    const int tq     = lane & 3;
    const int lo7    = lane & 7;
    const int l3     = (lane >> 3) & 1;
    const int hi     = lane >> 4;
    const int warp_m = warp >> 2;
    const int warp_n = warp & 3;
    const int rowBase = blockIdx.y * GBM;
    const int colBase = blockIdx.x * GBN;

    const __half* Ap = A + (size_t)rowBase * K;
    const __half* Wp = W + (size_t)colBase * K;

    float acc[4][4][4];
#pragma unroll
    for (int mt = 0; mt < 4; mt++)
#pragma unroll
        for (int nt = 0; nt < 4; nt++)
#pragma unroll
            for (int r = 0; r < 4; r++) acc[mt][nt][r] = 0.f;

    const uint32_t sbase = s2u(smem);
    const uint32_t aRow = (uint32_t)((warp_m * 64 + lo7 + 8 * l3) * 128);
    const uint32_t bRow = (uint32_t)((warp_n * 32 + lo7) * 128);

    const int NITER = K >> 6;              // 8 for K=512

    auto issue = [&](int it) {
        char* aS = smem + (it % 3) * STAGE_B;
        char* bS = aS + TILE_B;
        const int k0 = it * GBK;
#pragma unroll
        for (int i = 0; i < 4; i++) {
            int f   = tid + i * 256;
            int r   = f >> 3;
            int seg = f & 7;
            int dst = r * 128 + ((seg ^ (r & 7)) * 16);
            cp16(aS + dst, Ap + (size_t)r * K + k0 + seg * 8);
            cp16(bS + dst, Wp + (size_t)r * K + k0 + seg * 8);
        }
    };

    issue(0);
    asm volatile("cp.async.commit_group;\n");
    issue(1);
    asm volatile("cp.async.commit_group;\n");

    for (int it = 0; it < NITER; it++) {
        if (it + 1 < NITER)
            asm volatile("cp.async.wait_group 1;\n");
        else
            asm volatile("cp.async.wait_group 0;\n");
        __syncthreads();
        if (it + 2 < NITER) {
            issue(it + 2);
            asm volatile("cp.async.commit_group;\n");
        }

        const uint32_t aBase = sbase + (uint32_t)((it % 3) * STAGE_B);
        const uint32_t bBase = aBase + TILE_B;

#pragma unroll
        for (int ks = 0; ks < 4; ks++) {
            const uint32_t aSeg = (uint32_t)(((2 * ks + hi) ^ lo7) * 16);
            const uint32_t bSeg = (uint32_t)(((2 * ks + l3) ^ lo7) * 16);
            uint32_t af[4][4];
            uint32_t bf[4][2];
#pragma unroll
            for (int mt = 0; mt < 4; mt++)
                ldsm_x4(af[mt], aBase + aRow + (uint32_t)(mt * 16 * 128) + aSeg);
#pragma unroll
            for (int nt = 0; nt < 4; nt++)
                ldsm_x2(bf[nt], bBase + bRow + (uint32_t)(nt * 8 * 128) + bSeg);
#pragma unroll
            for (int mt = 0; mt < 4; mt++)
#pragma unroll
                for (int nt = 0; nt < 4; nt++)
                    mma_f16(acc[mt][nt], af[mt], bf[nt]);
        }
        // no trailing barrier: stage reuse protected by next iter's sync
    }

#pragma unroll
    for (int mt = 0; mt < 4; mt++) {
        int r0 = rowBase + warp_m * 64 + mt * 16 + quad;
#pragma unroll
        for (int nt = 0; nt < 4; nt++) {
            int c = colBase + warp_n * 32 + nt * 8 + 2 * tq;
            float2 bv = *(const float2*)&bias[c];
            float ox0 = (acc[mt][nt][0] + bv.x) * outScale;
            float oy0 = (acc[mt][nt][1] + bv.y) * outScale;
            float ox1 = (acc[mt][nt][2] + bv.x) * outScale;
            float oy1 = (acc[mt][nt][3] + bv.y) * outScale;
            if (outHalf) {
                __half* Ch = (__half*)Cv;
                *(uint32_t*)&Ch[(size_t)r0 * N + c] =
                    h2u(__floats2half2_rn(ox0, oy0));
                *(uint32_t*)&Ch[(size_t)(r0 + 8) * N + c] =
                    h2u(__floats2half2_rn(ox1, oy1));
            } else {
                float* Cf = (float*)Cv;
                *(float2*)&Cf[(size_t)r0 * N + c]       = make_float2(ox0, oy0);
                *(float2*)&Cf[(size_t)(r0 + 8) * N + c] = make_float2(ox1, oy1);
            }
        }
    }
}

// =======================================================================
// FP16 fused window attention (unchanged from R13, best-known)
// =======================================================================
#define QKH 72
#define PVH 152
#define SSW 132
#define R1_W   4940
#define R2_W   5184
#define OFF_S  (R1_W + R2_W)
#define ATTN_W (OFF_S + N_Q * SSW)
#define ATTN_SMEM_BYTES (ATTN_W * 4)

__global__ __launch_bounds__(256, 3) void attn_kernel(
    const int* __restrict__ nW_ptr,
    __half* __restrict__ out)
{
    extern __shared__ float sm[];
    __half* qh  = (__half*)sm;
    __half* ph  = (__half*)sm;
    __half* kh  = (__half*)(sm + R1_W);
    __half* vh  = (__half*)(sm + R1_W);
    float*  S   = sm + OFF_S;

    const int bid  = blockIdx.x;
    const int b    = bid >> 3;
    const int h    = bid & 7;
    const int tid  = threadIdx.x;
    const int warp = tid >> 5;
    const int lane = tid & 31;
    const int quad = lane >> 2;
    const int tq   = lane & 3;
    const int lo7  = lane & 7;
    const int l3   = (lane >> 3) & 1;
    const int hi   = lane >> 4;
    const int wm   = warp >> 1;
    const int wn   = warp & 1;
    const int nW   = *nW_ptr;

    const int mc = (nW < 4) ? nW : 4;
    const int w  = b % nW;
    int cls = 0;
    if (w < mc)            cls = 1 + w;
    else if (w >= nW - mc) cls = 5 + (w - nW + 4);
    const float* T = g_bias + ((size_t)(cls * NH + h)) * N_Q * 132;

    for (int idx = tid; idx < (N_Q * SSW) / 4; idx += 256)
        *(float4*)&S[idx * 4] = *(const float4*)&T[idx * 4];

    for (int idx = tid; idx < N_Q * 8; idx += 256) {
        int i = idx >> 3, c = idx & 7;
        uint4 v = *(const uint4*)&h_q[((size_t)(b * N_Q + i)) * CDIM + h * HDIM + c * 8];
        *(uint4*)&qh[i * QKH + c * 8] = v;
    }
    for (int idx = tid; idx < 144 * 8; idx += 256) {
        int j = idx >> 3, c = idx & 7;
        uint4 v = {0u, 0u, 0u, 0u};
        if (j < M_KV)
            v = *(const uint4*)&h_kv[((size_t)(b * M_KV + j)) * (2 * CDIM)
                                     + h * HDIM + c * 8];
        *(uint4*)&kh[j * QKH + c * 8] = v;
    }
    __syncthreads();

    const int nbase = wn * 72;
    float acc[9][4];
#pragma unroll
    for (int nt = 0; nt < 9; nt++)
#pragma unroll
        for (int r = 0; r < 4; r++) acc[nt][r] = 0.f;

    {
        const uint32_t qB = s2u(qh) + (uint32_t)((wm * 16 + lo7 + 8 * l3) * 144);
        const uint32_t kB = s2u(kh) + (uint32_t)((nbase + lo7) * 144);
#pragma unroll
        for (int ks = 0; ks < 4; ks++) {
            uint32_t a[4];
            ldsm_x4(a, qB + (uint32_t)(ks * 32 + 16 * hi));
#pragma unroll
            for (int nt = 0; nt < 9; nt++) {
                uint32_t bfr[2];
                ldsm_x2(bfr, kB + (uint32_t)(nt * 8 * 144 + ks * 32 + 16 * l3));
                mma_f16(acc[nt], a, bfr);
            }
        }
    }

    float s64 = 0.f;
    if (tid < M_KV) {
#pragma unroll 8
        for (int d = 0; d < HDIM; d++)
            s64 += __half2float(qh[64 * QKH + d]) * __half2float(kh[tid * QKH + d]);
    }
    __syncthreads();

#pragma unroll
    for (int nt = 0; nt < 9; nt++) {
        int j0 = nbase + nt * 8 + 2 * tq;
        int i0 = wm * 16 + quad;
#pragma unroll
        for (int e = 0; e < 4; e++) {
            int i = i0 + (e >> 1) * 8;
            int j = j0 + (e & 1);
            if (j >= M_KV) continue;
            S[i * SSW + j] = acc[nt][e] + S[i * SSW + j];
        }
    }
    if (tid < M_KV)
        S[64 * SSW + tid] = s64 + S[64 * SSW + tid];

    for (int idx = tid; idx < N_Q * 15; idx += 256) {
        int i = idx / 15, c = M_KV + idx % 15;
        ph[i * PVH + c] = __float2half(0.f);
    }
    for (int idx = tid; idx < 144 * 8; idx += 256) {
        int j = idx >> 3, c = idx & 7;
        uint4 v = {0u, 0u, 0u, 0u};
        if (j < M_KV)
            v = *(const uint4*)&h_kv[((size_t)(b * M_KV + j)) * (2 * CDIM)
                                     + CDIM + h * HDIM + c * 8];
        *(uint4*)&vh[j * QKH + c * 8] = v;
    }
    __syncthreads();

    for (int r = warp; r < N_Q; r += 8) {
        float mx = -FLT_MAX;
        for (int c = lane; c < M_KV; c += 32) mx = fmaxf(mx, S[r * SSW + c]);
#pragma unroll
        for (int o = 16; o; o >>= 1) mx = fmaxf(mx, __shfl_xor_sync(0xffffffffu, mx, o));
        float sum = 0.f;
        float ev[5];
#pragma unroll
        for (int t = 0; t < 5; t++) {
            int c = lane + t * 32;
            float e = (c < M_KV) ? __expf(S[r * SSW + c] - mx) : 0.f;
            ev[t] = e;
            sum += e;
        }
#pragma unroll
        for (int o = 16; o; o >>= 1) sum += __shfl_xor_sync(0xffffffffu, sum, o);
        float inv = 1.0f / sum;
#pragma unroll
        for (int t = 0; t < 5; t++) {
            int c = lane + t * 32;
            if (c < M_KV) ph[r * PVH + c] = __float2half_rn(ev[t] * inv);
        }
    }
    __syncthreads();

    float acc2[4][4];
#pragma unroll
    for (int nt = 0; nt < 4; nt++)
#pragma unroll
        for (int r = 0; r < 4; r++) acc2[nt][r] = 0.f;

    {
        const uint32_t pB = s2u(ph) + (uint32_t)((wm * 16 + lo7 + 8 * l3) * 304);
        const uint32_t vB = s2u(vh) + (uint32_t)((lane & 15) * 144 + wn * 64);
#pragma unroll
        for (int ks = 0; ks < 9; ks++) {
            uint32_t a[4];
            ldsm_x4(a, pB + (uint32_t)(ks * 32 + 16 * hi));
#pragma unroll
            for (int nt = 0; nt < 4; nt++) {
                uint32_t bfr[2];
                ldsm_x2_trans(bfr, vB + (uint32_t)(ks * 16 * 144 + nt * 16));
                mma_f16(acc2[nt], a, bfr);
            }
        }
    }

    float o64 = 0.f;
    if (tid < HDIM) {
        for (int j = 0; j < M_KV; j++)
            o64 += __half2float(ph[64 * PVH + j]) * __half2float(vh[j * QKH + tid]);
    }

#pragma unroll
    for (int nt = 0; nt < 4; nt++) {
        int i0 = wm * 16 + quad;
        int d0 = wn * 32 + nt * 8 + 2 * tq;
        *(uint32_t*)&out[((size_t)(b * N_Q + i0)) * CDIM + h * HDIM + d0] =
            h2u(__floats2half2_rn(acc2[nt][0], acc2[nt][1]));
        *(uint32_t*)&out[((size_t)(b * N_Q + i0 + 8)) * CDIM + h * HDIM + d0] =
            h2u(__floats2half2_rn(acc2[nt][2], acc2[nt][3]));
    }
    if (tid < HDIM)
        out[((size_t)(b * N_Q + 64)) * CDIM + h * HDIM + tid] = __float2half_rn(o64);
}

// =======================================================================
// kernel_launch
// =======================================================================
extern "C" void kernel_launch(void* const* d_in, const int* in_sizes, int n_in,
                              void* d_out, int out_size)
{
    const float* x    = (const float*)d_in[0];
    const float* x_   = (const float*)d_in[1];
    const int*   mask_left  = (const int*)d_in[2];
    const int*   mask_right = (const int*)d_in[3];
    const int*   nW   = (const int*)d_in[4];
    const float* rel_table = (const float*)d_in[5];
    const float* cls_self  = (const float*)d_in[6];
    const float* cls_up    = (const float*)d_in[7];
    const float* cls_down  = (const float*)d_in[8];
    const float* Wq   = (const float*)d_in[9];
    const float* bq   = (const float*)d_in[10];
    const float* Wkv  = (const float*)d_in[11];
    const float* bkv  = (const float*)d_in[12];
    const float* Wp   = (const float*)d_in[13];
    const float* bp   = (const float*)d_in[14];
    float* out = (float*)d_out;

    const int Bq = in_sizes[0] / (N_Q * CDIM);   // 512

    __half *hx, *hx_, *hwq, *hwkv, *hwp, *hq, *hkv, *hatt;
    cudaGetSymbolAddress((void**)&hx,   h_x);
    cudaGetSymbolAddress((void**)&hx_,  h_x_);
    cudaGetSymbolAddress((void**)&hwq,  h_wq);
    cudaGetSymbolAddress((void**)&hwkv, h_wkv);
    cudaGetSymbolAddress((void**)&hwp,  h_wp);
    cudaGetSymbolAddress((void**)&hq,   h_q);
    cudaGetSymbolAddress((void**)&hkv,  h_kv);
    cudaGetSymbolAddress((void**)&hatt, h_att);

    cudaFuncSetAttribute(gemm_f16_kernel,
                         cudaFuncAttributeMaxDynamicSharedMemorySize,
                         GEMM_SMEM_BYTES);
    cudaFuncSetAttribute(attn_kernel,
                         cudaFuncAttributeMaxDynamicSharedMemorySize,
                         ATTN_SMEM_BYTES);

    // 0a) bias+mask tables
    build_bias_kernel<<<9 * NH, 256>>>(rel_table, cls_self, cls_up, cls_down,
                                       mask_left, mask_right);
    // 0b) fp32 -> fp16 pre-pass
    {
        int n0 = Bq * N_Q * CDIM / 8;
        int n1 = Bq * M_KV * CDIM / 8;
        int n2 = CDIM * CDIM / 8;
        int n3 = 2 * CDIM * CDIM / 8;
        int n4 = CDIM * CDIM / 8;
        int total = n0 + n1 + n2 + n3 + n4;
        cvt_fp16_multi<<<(total + 255) / 256, 256>>>(
            x, hx, n0, x_, hx_, n1, Wq, hwq, n2, Wkv, hwkv, n3, Wp, hwp, n4);
    }

    // 1) q = (x @ Wq^T + bq) * 0.125 : M = 33280, N = 512 -> fp16
    {
        dim3 grid(CDIM / GBN, (Bq * N_Q) / GBM);          // (4, 260)
        gemm_f16_kernel<<<grid, 256, GEMM_SMEM_BYTES>>>(
            hx, hwq, bq, hq, CDIM, CDIM, 1, 0.125f);
    }
    // 2) kv = x_ @ Wkv^T + bkv : M = 66048, N = 1024 -> fp16
    {
        dim3 grid((2 * CDIM) / GBN, (Bq * M_KV) / GBM);   // (8, 516)
        gemm_f16_kernel<<<grid, 256, GEMM_SMEM_BYTES>>>(
            hx_, hwkv, bkv, hkv, CDIM, 2 * CDIM, 1, 1.0f);
    }
    // 3) fused fp16 attention -> h_att
    {
        attn_kernel<<<Bq * NH, 256, ATTN_SMEM_BYTES>>>(nW, hatt);
    }
    // 4) out = att @ Wp^T + bp : M = 33280, N = 512 -> fp32
    {
        dim3 grid(CDIM / GBN, (Bq * N_Q) / GBM);          // (4, 260)
        gemm_f16_kernel<<<grid, 256, GEMM_SMEM_BYTES>>>(
            hatt, hwp, bp, out, CDIM, CDIM, 0, 1.0f);
    }
}

// round 16
// speedup vs baseline: 1.1815x; 1.0775x over previous
#include <cuda_runtime.h>
#include <cuda_fp16.h>
#include <math.h>
#include <float.h>
#include <stdint.h>

// ---------------- problem constants (fixed by dataset) ----------------
#define N_Q   65      // n = 1+W
#define M_KV  129     // m = 1+R
#define NH    8       // heads
#define HDIM  64      // head dim
#define CDIM  512     // model dim (= H*HD)
#define BQMAX 512     // B_ = 512

// ---------------- scratch (device globals; no allocation) -------------
__device__ __half h_x  [(size_t)BQMAX * N_Q  * CDIM];
__device__ __half h_x_ [(size_t)BQMAX * M_KV * CDIM];
__device__ __half h_wq [(size_t)CDIM * CDIM];
__device__ __half h_wkv[(size_t)2 * CDIM * CDIM];
__device__ __half h_wp [(size_t)CDIM * CDIM];
__device__ __half h_q  [(size_t)BQMAX * N_Q  * CDIM];
__device__ __half h_kv [(size_t)BQMAX * M_KV * 2 * CDIM];
__device__ __half h_att[(size_t)BQMAX * N_Q  * CDIM];
// bias+mask tables: 9 window classes x 8 heads x 65 x 132 fp32
__device__ float g_bias[(size_t)9 * NH * N_Q * 132];

// ---------------- helpers ----------------------------------------------
__device__ __forceinline__ void mma_f16(float c[4], const uint32_t a[4],
                                        const uint32_t b[2]) {
    asm volatile(
        "mma.sync.aligned.m16n8k16.row.col.f32.f16.f16.f32 "
        "{%0,%1,%2,%3}, {%4,%5,%6,%7}, {%8,%9}, {%0,%1,%2,%3};"
        : "+f"(c[0]), "+f"(c[1]), "+f"(c[2]), "+f"(c[3])
        : "r"(a[0]), "r"(a[1]), "r"(a[2]), "r"(a[3]),
          "r"(b[0]), "r"(b[1]));
}
__device__ __forceinline__ void cp16(void* smem, const void* g) {
    uint32_t a = (uint32_t)__cvta_generic_to_shared(smem);
    asm volatile("cp.async.cg.shared.global [%0], [%1], 16;\n"
                 :: "r"(a), "l"(g));
}
__device__ __forceinline__ uint32_t h2u(__half2 h) {
    return *reinterpret_cast<uint32_t*>(&h);
}
__device__ __forceinline__ uint32_t s2u(const void* p) {
    return (uint32_t)__cvta_generic_to_shared(p);
}
__device__ __forceinline__ void ldsm_x4(uint32_t r[4], uint32_t addr) {
    asm volatile("ldmatrix.sync.aligned.m8n8.x4.shared.b16 {%0,%1,%2,%3}, [%4];"
                 : "=r"(r[0]), "=r"(r[1]), "=r"(r[2]), "=r"(r[3]) : "r"(addr));
}
__device__ __forceinline__ void ldsm_x2(uint32_t r[2], uint32_t addr) {
    asm volatile("ldmatrix.sync.aligned.m8n8.x2.shared.b16 {%0,%1}, [%2];"
                 : "=r"(r[0]), "=r"(r[1]) : "r"(addr));
}
__device__ __forceinline__ void ldsm_x2_trans(uint32_t r[2], uint32_t addr) {
    asm volatile("ldmatrix.sync.aligned.m8n8.x2.trans.shared.b16 {%0,%1}, [%2];"
                 : "=r"(r[0]), "=r"(r[1]) : "r"(addr));
}

// =======================================================================
// fp32 -> fp16 conversion pre-pass, all 5 tensors in ONE launch.
// =======================================================================
__global__ void cvt_fp16_multi(
    const float* __restrict__ s0, __half* __restrict__ d0, int n0,
    const float* __restrict__ s1, __half* __restrict__ d1, int n1,
    const float* __restrict__ s2, __half* __restrict__ d2, int n2,
    const float* __restrict__ s3, __half* __restrict__ d3, int n3,
    const float* __restrict__ s4, __half* __restrict__ d4, int n4)
{
    int i = blockIdx.x * blockDim.x + threadIdx.x;
    const float* s; __half* d; int l = i;
    if (l < n0)                  { s = s0; d = d0; }
    else if ((l -= n0) < n1)     { s = s1; d = d1; }
    else if ((l -= n1) < n2)     { s = s2; d = d2; }
    else if ((l -= n2) < n3)     { s = s3; d = d3; }
    else if ((l -= n3) < n4)     { s = s4; d = d4; }
    else return;
    const float4 v0 = ((const float4*)s)[l * 2];
    const float4 v1 = ((const float4*)s)[l * 2 + 1];
    uint4 o;
    o.x = h2u(__floats2half2_rn(v0.x, v0.y));
    o.y = h2u(__floats2half2_rn(v0.z, v0.w));
    o.z = h2u(__floats2half2_rn(v1.x, v1.y));
    o.w = h2u(__floats2half2_rn(v1.z, v1.w));
    ((uint4*)d)[l] = o;
}

// =======================================================================
// bias+mask table build: 72 blocks = (cls 0..8) x (h 0..7).
// =======================================================================
__global__ void build_bias_kernel(
    const float* __restrict__ rel, const float* __restrict__ self_,
    const float* __restrict__ up,  const float* __restrict__ down,
    const int* __restrict__ ml,    const int* __restrict__ mr)
{
    const int cls = blockIdx.x >> 3;
    const int h   = blockIdx.x & 7;
    float* dst = g_bias + ((size_t)(cls * NH + h)) * N_Q * 132;
    for (int idx = threadIdx.x; idx < N_Q * M_KV; idx += 256) {
        int i = idx / M_KV, j = idx % M_KV;
        float bias;
        if (i == 0)      bias = (j == 0) ? self_[h] : up[h * 128 + (j - 1)];
        else if (j == 0) bias = down[h * 64 + (i - 1)];
        else             bias = rel[(i - j + 127) * NH + h];
        if (cls >= 1 && cls <= 4) {
            if (ml[((cls - 1) * N_Q + i) * M_KV + j] == 1) bias = -FLT_MAX;
        } else if (cls >= 5) {
            if (mr[((cls - 5) * N_Q + i) * M_KV + j] == 1) bias = -FLT_MAX;
        }
        dst[i * 132 + j] = bias;
    }
    for (int idx = threadIdx.x; idx < N_Q * 3; idx += 256) {
        int i = idx / 3, c = M_KV + idx % 3;
        dst[i * 132 + c] = 0.f;
    }
}

// =======================================================================
// FP16 tensor-core GEMM — R13 exact (best measured): 2-stage cp.async,
// BM=128, BN=128, BK=64, 256 thr, 2 CTA/SM, warp tile 64x32, ldmatrix.
//   C[M,N] = (A[M,K] @ W[N,K]^T + bias[N]) * outScale
// =======================================================================
#define GBM 128
#define GBN 128
#define GBK 64
#define TILE_B   (128 * 128)
#define STAGE_B  (2 * TILE_B)
#define GEMM_SMEM_BYTES (2 * STAGE_B)         // 65536

__global__ __launch_bounds__(256, 2) void gemm_f16_kernel(
    const __half* __restrict__ A, const __half* __restrict__ W,
    const float* __restrict__ bias, void* __restrict__ Cv,
    int K, int N, int outHalf, float outScale)
{
    extern __shared__ char smem[];

    const int tid    = threadIdx.x;
    const int warp   = tid >> 5;
    const int lane   = tid & 31;
    const int quad   = lane >> 2;
    const int tq     = lane & 3;
    const int lo7    = lane & 7;
    const int l3     = (lane >> 3) & 1;
    const int hi     = lane >> 4;
    const int warp_m = warp >> 2;
    const int warp_n = warp & 3;
    const int rowBase = blockIdx.y * GBM;
    const int colBase = blockIdx.x * GBN;

    const __half* Ap = A + (size_t)rowBase * K;
    const __half* Wp = W + (size_t)colBase * K;

    float acc[4][4][4];
#pragma unroll
    for (int mt = 0; mt < 4; mt++)
#pragma unroll
        for (int nt = 0; nt < 4; nt++)
#pragma unroll
            for (int r = 0; r < 4; r++) acc[mt][nt][r] = 0.f;

    const uint32_t sbase = s2u(smem);
    const uint32_t aRow = (uint32_t)((warp_m * 64 + lo7 + 8 * l3) * 128);
    const uint32_t bRow = (uint32_t)((warp_n * 32 + lo7) * 128);

    const int NITER = K >> 6;

    auto issue = [&](int it) {
        char* aS = smem + (it & 1) * STAGE_B;
        char* bS = aS + TILE_B;
        const int k0 = it * GBK;
#pragma unroll
        for (int i = 0; i < 4; i++) {
            int f   = tid + i * 256;
            int r   = f >> 3;
            int seg = f & 7;
            int dst = r * 128 + ((seg ^ (r & 7)) * 16);
            cp16(aS + dst, Ap + (size_t)r * K + k0 + seg * 8);
            cp16(bS + dst, Wp + (size_t)r * K + k0 + seg * 8);
        }
    };

    issue(0);
    asm volatile("cp.async.commit_group;\n");

    for (int it = 0; it < NITER; it++) {
        if (it + 1 < NITER) {
            issue(it + 1);
            asm volatile("cp.async.commit_group;\n");
            asm volatile("cp.async.wait_group 1;\n");
        } else {
            asm volatile("cp.async.wait_group 0;\n");
        }
        __syncthreads();

        const uint32_t aBase = sbase + (it & 1) * STAGE_B;
        const uint32_t bBase = aBase + TILE_B;

#pragma unroll
        for (int ks = 0; ks < 4; ks++) {
            const uint32_t aSeg = (uint32_t)(((2 * ks + hi) ^ lo7) * 16);
            const uint32_t bSeg = (uint32_t)(((2 * ks + l3) ^ lo7) * 16);
            uint32_t af[4][4];
            uint32_t bf[4][2];
#pragma unroll
            for (int mt = 0; mt < 4; mt++)
                ldsm_x4(af[mt], aBase + aRow + (uint32_t)(mt * 16 * 128) + aSeg);
#pragma unroll
            for (int nt = 0; nt < 4; nt++)
                ldsm_x2(bf[nt], bBase + bRow + (uint32_t)(nt * 8 * 128) + bSeg);
#pragma unroll
            for (int mt = 0; mt < 4; mt++)
#pragma unroll
                for (int nt = 0; nt < 4; nt++)
                    mma_f16(acc[mt][nt], af[mt], bf[nt]);
        }
        __syncthreads();
    }

#pragma unroll
    for (int mt = 0; mt < 4; mt++) {
        int r0 = rowBase + warp_m * 64 + mt * 16 + quad;
#pragma unroll
        for (int nt = 0; nt < 4; nt++) {
            int c = colBase + warp_n * 32 + nt * 8 + 2 * tq;
            float2 bv = *(const float2*)&bias[c];
            float ox0 = (acc[mt][nt][0] + bv.x) * outScale;
            float oy0 = (acc[mt][nt][1] + bv.y) * outScale;
            float ox1 = (acc[mt][nt][2] + bv.x) * outScale;
            float oy1 = (acc[mt][nt][3] + bv.y) * outScale;
            if (outHalf) {
                __half* Ch = (__half*)Cv;
                *(uint32_t*)&Ch[(size_t)r0 * N + c] =
                    h2u(__floats2half2_rn(ox0, oy0));
                *(uint32_t*)&Ch[(size_t)(r0 + 8) * N + c] =
                    h2u(__floats2half2_rn(ox1, oy1));
            } else {
                float* Cf = (float*)Cv;
                *(float2*)&Cf[(size_t)r0 * N + c]       = make_float2(ox0, oy0);
                *(float2*)&Cf[(size_t)(r0 + 8) * N + c] = make_float2(ox1, oy1);
            }
        }
    }
}

// =======================================================================
// FP16 fused window attention — REGISTER SOFTMAX (no fp32 S region).
// smem (words):
//   [0, 4940):          q fp16 [65][72h] -> P fp16 [65][152h] (overlay)
//   [4940, 10124):      k fp16 [144][72h] -> v fp16 [144][72h] (overlay)
//   [10124, 18704):     bias table fp32 [65][132] (read-only)
//   [18704, 18832):     rmax [2][64]
//   [18832, 18960):     rsum [2][64]
//   [18960, 18968):     b64m[5] (pad 8)
//   [18968, 18976):     b64s[5] (pad 8)
// =======================================================================
#define QKH 72
#define PVH 152
#define R1_W   4940
#define R2_W   5184
#define OFF_B  (R1_W + R2_W)          // 10124
#define OFF_RM (OFF_B + N_Q * 132)    // 18704
#define OFF_RS (OFF_RM + 128)         // 18832
#define OFF_M64 (OFF_RS + 128)        // 18960
#define OFF_S64 (OFF_M64 + 8)         // 18968
#define ATTN_W  (OFF_S64 + 8)         // 18976
#define ATTN_SMEM_BYTES (ATTN_W * 4)  // 75904

__global__ __launch_bounds__(256, 3) void attn_kernel(
    const int* __restrict__ nW_ptr,
    __half* __restrict__ out)
{
    extern __shared__ float sm[];
    __half* qh  = (__half*)sm;
    __half* ph  = (__half*)sm;
    __half* kh  = (__half*)(sm + R1_W);
    __half* vh  = (__half*)(sm + R1_W);
    float*  Bs  = sm + OFF_B;
    float*  rmx = sm + OFF_RM;
    float*  rsm = sm + OFF_RS;
    float*  b64m = sm + OFF_M64;
    float*  b64s = sm + OFF_S64;

    const int bid  = blockIdx.x;
    const int b    = bid >> 3;
    const int h    = bid & 7;
    const int tid  = threadIdx.x;
    const int warp = tid >> 5;
    const int lane = tid & 31;
    const int quad = lane >> 2;
    const int tq   = lane & 3;
    const int lo7  = lane & 7;
    const int l3   = (lane >> 3) & 1;
    const int hi   = lane >> 4;
    const int wm   = warp >> 1;
    const int wn   = warp & 1;
    const int nW   = *nW_ptr;

    const int mc = (nW < 4) ? nW : 4;
    const int w  = b % nW;
    int cls = 0;
    if (w < mc)            cls = 1 + w;
    else if (w >= nW - mc) cls = 5 + (w - nW + 4);
    const float* T = g_bias + ((size_t)(cls * NH + h)) * N_Q * 132;

    // ---- preload bias table (read-only), q, k
    for (int idx = tid; idx < (N_Q * 132) / 4; idx += 256)
        *(float4*)&Bs[idx * 4] = *(const float4*)&T[idx * 4];
    for (int idx = tid; idx < N_Q * 8; idx += 256) {
        int i = idx >> 3, c = idx & 7;
        uint4 v = *(const uint4*)&h_q[((size_t)(b * N_Q + i)) * CDIM + h * HDIM + c * 8];
        *(uint4*)&qh[i * QKH + c * 8] = v;
    }
    for (int idx = tid; idx < 144 * 8; idx += 256) {
        int j = idx >> 3, c = idx & 7;
        uint4 v = {0u, 0u, 0u, 0u};
        if (j < M_KV)
            v = *(const uint4*)&h_kv[((size_t)(b * M_KV + j)) * (2 * CDIM)
                                     + h * HDIM + c * 8];
        *(uint4*)&kh[j * QKH + c * 8] = v;
    }
    __syncthreads();                                   // sync 1

    // ---- QK^T mma: rows 0..63 (9 n-tiles per warp half)
    const int nbase = wn * 72;
    const int i0r   = wm * 16 + quad;
    float acc[9][4];
#pragma unroll
    for (int nt = 0; nt < 9; nt++)
#pragma unroll
        for (int r = 0; r < 4; r++) acc[nt][r] = 0.f;

    {
        const uint32_t qB = s2u(qh) + (uint32_t)((wm * 16 + lo7 + 8 * l3) * 144);
        const uint32_t kB = s2u(kh) + (uint32_t)((nbase + lo7) * 144);
#pragma unroll
        for (int ks = 0; ks < 4; ks++) {
            uint32_t a[4];
            ldsm_x4(a, qB + (uint32_t)(ks * 32 + 16 * hi));
#pragma unroll
            for (int nt = 0; nt < 9; nt++) {
                uint32_t bfr[2];
                ldsm_x2(bfr, kB + (uint32_t)(nt * 8 * 144 + ks * 32 + 16 * l3));
                mma_f16(acc[nt], a, bfr);
            }
        }
    }

    // ---- row 64 scalar logits (+ bias, includes mask)
    float s64v = 0.f;
    if (tid < M_KV) {
#pragma unroll 8
        for (int d = 0; d < HDIM; d++)
            s64v += __half2float(qh[64 * QKH + d]) * __half2float(kh[tid * QKH + d]);
        s64v += Bs[64 * 132 + tid];
    }

    // ---- bias add + in-register row max (rows 0..63)
    float m0 = -FLT_MAX, m1 = -FLT_MAX;
#pragma unroll
    for (int nt = 0; nt < 9; nt++) {
        int j0 = nbase + nt * 8 + 2 * tq;
        if (j0 < M_KV) {
            acc[nt][0] += Bs[i0r * 132 + j0];
            acc[nt][2] += Bs[(i0r + 8) * 132 + j0];
        } else { acc[nt][0] = -INFINITY; acc[nt][2] = -INFINITY; }
        if (j0 + 1 < M_KV) {
            acc[nt][1] += Bs[i0r * 132 + j0 + 1];
            acc[nt][3] += Bs[(i0r + 8) * 132 + j0 + 1];
        } else { acc[nt][1] = -INFINITY; acc[nt][3] = -INFINITY; }
        m0 = fmaxf(m0, fmaxf(acc[nt][0], acc[nt][1]));
        m1 = fmaxf(m1, fmaxf(acc[nt][2], acc[nt][3]));
    }
    m0 = fmaxf(m0, __shfl_xor_sync(0xffffffffu, m0, 1));
    m0 = fmaxf(m0, __shfl_xor_sync(0xffffffffu, m0, 2));
    m1 = fmaxf(m1, __shfl_xor_sync(0xffffffffu, m1, 1));
    m1 = fmaxf(m1, __shfl_xor_sync(0xffffffffu, m1, 2));
    if (tq == 0) {
        rmx[wn * 64 + i0r]     = m0;
        rmx[wn * 64 + i0r + 8] = m1;
    }
    // ---- row 64 max partials
    if (tid < 128) {
        float m = s64v;
#pragma unroll
        for (int o = 16; o; o >>= 1) m = fmaxf(m, __shfl_xor_sync(0xffffffffu, m, o));
        if (lane == 0) b64m[warp] = m;
    } else if (tid == 128) b64m[4] = s64v;
    __syncthreads();                                   // sync 2 (k reads done)

    // ---- load v natural [j][d] (overwrites k)
    for (int idx = tid; idx < 144 * 8; idx += 256) {
        int j = idx >> 3, c = idx & 7;
        uint4 v = {0u, 0u, 0u, 0u};
        if (j < M_KV)
            v = *(const uint4*)&h_kv[((size_t)(b * M_KV + j)) * (2 * CDIM)
                                     + CDIM + h * HDIM + c * 8];
        *(uint4*)&vh[j * QKH + c * 8] = v;
    }

    // ---- exp + in-register row sum
    const float M0 = fmaxf(rmx[i0r],     rmx[64 + i0r]);
    const float M1 = fmaxf(rmx[i0r + 8], rmx[64 + i0r + 8]);
    float s0 = 0.f, s1 = 0.f;
#pragma unroll
    for (int nt = 0; nt < 9; nt++) {
        acc[nt][0] = __expf(acc[nt][0] - M0);
        acc[nt][1] = __expf(acc[nt][1] - M0);
        acc[nt][2] = __expf(acc[nt][2] - M1);
        acc[nt][3] = __expf(acc[nt][3] - M1);
        s0 += acc[nt][0] + acc[nt][1];
        s1 += acc[nt][2] + acc[nt][3];
    }
    s0 += __shfl_xor_sync(0xffffffffu, s0, 1);
    s0 += __shfl_xor_sync(0xffffffffu, s0, 2);
    s1 += __shfl_xor_sync(0xffffffffu, s1, 1);
    s1 += __shfl_xor_sync(0xffffffffu, s1, 2);
    if (tq == 0) {
        rsm[wn * 64 + i0r]     = s0;
        rsm[wn * 64 + i0r + 8] = s1;
    }
    // ---- row 64 exp + sum partials
    float e64 = 0.f;
    {
        float m64 = fmaxf(fmaxf(fmaxf(b64m[0], b64m[1]),
                                fmaxf(b64m[2], b64m[3])), b64m[4]);
        if (tid < M_KV) e64 = __expf(s64v - m64);
        if (tid < 128) {
            float s = e64;
#pragma unroll
            for (int o = 16; o; o >>= 1) s += __shfl_xor_sync(0xffffffffu, s, o);
            if (lane == 0) b64s[warp] = s;
        } else if (tid == 128) b64s[4] = e64;
    }
    // ---- row 64 P pad (cols 129..143)
    if (tid >= M_KV && tid < 144) ph[64 * PVH + tid] = __float2half(0.f);
    __syncthreads();                                   // sync 3

    // ---- write fp16 P (all cols 0..143 of rows 0..63 covered; invalid->0)
    {
        const float inv0 = 1.0f / (rsm[i0r]     + rsm[64 + i0r]);
        const float inv1 = 1.0f / (rsm[i0r + 8] + rsm[64 + i0r + 8]);
#pragma unroll
        for (int nt = 0; nt < 9; nt++) {
            int j0 = nbase + nt * 8 + 2 * tq;
            float v00 = (j0     < M_KV) ? acc[nt][0] * inv0 : 0.f;
            float v01 = (j0 + 1 < M_KV) ? acc[nt][1] * inv0 : 0.f;
            float v10 = (j0     < M_KV) ? acc[nt][2] * inv1 : 0.f;
            float v11 = (j0 + 1 < M_KV) ? acc[nt][3] * inv1 : 0.f;
            *(uint32_t*)&ph[i0r * PVH + j0] =
                h2u(__floats2half2_rn(v00, v01));
            *(uint32_t*)&ph[(i0r + 8) * PVH + j0] =
                h2u(__floats2half2_rn(v10, v11));
        }
        // row 64
        float tot64 = b64s[0] + b64s[1] + b64s[2] + b64s[3] + b64s[4];
        if (tid < M_KV)
            ph[64 * PVH + tid] = __float2half_rn(e64 * (1.0f / tot64));
    }
    __syncthreads();                                   // sync 4

    // ---- PV: K = 144 -> 9 x k16; B via ldmatrix.trans from v[j][d]
    float acc2[4][4];
#pragma unroll
    for (int nt = 0; nt < 4; nt++)
#pragma unroll
        for (int r = 0; r < 4; r++) acc2[nt][r] = 0.f;

    {
        const uint32_t pB = s2u(ph) + (uint32_t)((wm * 16 + lo7 + 8 * l3) * 304);
        const uint32_t vB = s2u(vh) + (uint32_t)((lane & 15) * 144 + wn * 64);
#pragma unroll
        for (int ks = 0; ks < 9; ks++) {
            uint32_t a[4];
            ldsm_x4(a, pB + (uint32_t)(ks * 32 + 16 * hi));
#pragma unroll
            for (int nt = 0; nt < 4; nt++) {
                uint32_t bfr[2];
                ldsm_x2_trans(bfr, vB + (uint32_t)(ks * 16 * 144 + nt * 16));
                mma_f16(acc2[nt], a, bfr);
            }
        }
    }

    // ---- row 64 scalar PV (v natural layout)
    float o64 = 0.f;
    if (tid < HDIM) {
        for (int j = 0; j < M_KV; j++)
            o64 += __half2float(ph[64 * PVH + j]) * __half2float(vh[j * QKH + tid]);
    }

#pragma unroll
    for (int nt = 0; nt < 4; nt++) {
        int i0 = wm * 16 + quad;
        int d0 = wn * 32 + nt * 8 + 2 * tq;
        *(uint32_t*)&out[((size_t)(b * N_Q + i0)) * CDIM + h * HDIM + d0] =
            h2u(__floats2half2_rn(acc2[nt][0], acc2[nt][1]));
        *(uint32_t*)&out[((size_t)(b * N_Q + i0 + 8)) * CDIM + h * HDIM + d0] =
            h2u(__floats2half2_rn(acc2[nt][2], acc2[nt][3]));
    }
    if (tid < HDIM)
        out[((size_t)(b * N_Q + 64)) * CDIM + h * HDIM + tid] = __float2half_rn(o64);
}

// =======================================================================
// kernel_launch
// =======================================================================
extern "C" void kernel_launch(void* const* d_in, const int* in_sizes, int n_in,
                              void* d_out, int out_size)
{
    const float* x    = (const float*)d_in[0];
    const float* x_   = (const float*)d_in[1];
    const int*   mask_left  = (const int*)d_in[2];
    const int*   mask_right = (const int*)d_in[3];
    const int*   nW   = (const int*)d_in[4];
    const float* rel_table = (const float*)d_in[5];
    const float* cls_self  = (const float*)d_in[6];
    const float* cls_up    = (const float*)d_in[7];
    const float* cls_down  = (const float*)d_in[8];
    const float* Wq   = (const float*)d_in[9];
    const float* bq   = (const float*)d_in[10];
    const float* Wkv  = (const float*)d_in[11];
    const float* bkv  = (const float*)d_in[12];
    const float* Wp   = (const float*)d_in[13];
    const float* bp   = (const float*)d_in[14];
    float* out = (float*)d_out;

    const int Bq = in_sizes[0] / (N_Q * CDIM);   // 512

    __half *hx, *hx_, *hwq, *hwkv, *hwp, *hq, *hkv, *hatt;
    cudaGetSymbolAddress((void**)&hx,   h_x);
    cudaGetSymbolAddress((void**)&hx_,  h_x_);
    cudaGetSymbolAddress((void**)&hwq,  h_wq);
    cudaGetSymbolAddress((void**)&hwkv, h_wkv);
    cudaGetSymbolAddress((void**)&hwp,  h_wp);
    cudaGetSymbolAddress((void**)&hq,   h_q);
    cudaGetSymbolAddress((void**)&hkv,  h_kv);
    cudaGetSymbolAddress((void**)&hatt, h_att);

    cudaFuncSetAttribute(gemm_f16_kernel,
                         cudaFuncAttributeMaxDynamicSharedMemorySize,
                         GEMM_SMEM_BYTES);
    cudaFuncSetAttribute(attn_kernel,
                         cudaFuncAttributeMaxDynamicSharedMemorySize,
                         ATTN_SMEM_BYTES);

    // 0a) bias+mask tables
    build_bias_kernel<<<9 * NH, 256>>>(rel_table, cls_self, cls_up, cls_down,
                                       mask_left, mask_right);
    // 0b) fp32 -> fp16 pre-pass
    {
        int n0 = Bq * N_Q * CDIM / 8;
        int n1 = Bq * M_KV * CDIM / 8;
        int n2 = CDIM * CDIM / 8;
        int n3 = 2 * CDIM * CDIM / 8;
        int n4 = CDIM * CDIM / 8;
        int total = n0 + n1 + n2 + n3 + n4;
        cvt_fp16_multi<<<(total + 255) / 256, 256>>>(
            x, hx, n0, x_, hx_, n1, Wq, hwq, n2, Wkv, hwkv, n3, Wp, hwp, n4);
    }

    // 1) q = (x @ Wq^T + bq) * 0.125 : M = 33280, N = 512 -> fp16
    {
        dim3 grid(CDIM / GBN, (Bq * N_Q) / GBM);          // (4, 260)
        gemm_f16_kernel<<<grid, 256, GEMM_SMEM_BYTES>>>(
            hx, hwq, bq, hq, CDIM, CDIM, 1, 0.125f);
    }
    // 2) kv = x_ @ Wkv^T + bkv : M = 66048, N = 1024 -> fp16
    {
        dim3 grid((2 * CDIM) / GBN, (Bq * M_KV) / GBM);   // (8, 516)
        gemm_f16_kernel<<<grid, 256, GEMM_SMEM_BYTES>>>(
            hx_, hwkv, bkv, hkv, CDIM, 2 * CDIM, 1, 1.0f);
    }
    // 3) fused fp16 attention (register softmax) -> h_att
    {
        attn_kernel<<<Bq * NH, 256, ATTN_SMEM_BYTES>>>(nW, hatt);
    }
    // 4) out = att @ Wp^T + bp : M = 33280, N = 512 -> fp32
    {
        dim3 grid(CDIM / GBN, (Bq * N_Q) / GBM);          // (4, 260)
        gemm_f16_kernel<<<grid, 256, GEMM_SMEM_BYTES>>>(
            hatt, hwp, bp, out, CDIM, CDIM, 0, 1.0f);
    }
}